// round 1
// baseline (speedup 1.0000x reference)
#include <cuda_runtime.h>
#include <math.h>

#define BDIM 4096
#define INDIM 1024
#define HDIM 2048
#define OUTDIM 1024
#define EDIM 16
// sum_e ceil(n_e/128) <= 4096/128 + 16 = 48
#define MAX_TILES 48

// Scratch (no allocation allowed) — 64 MB of __device__ globals.
__device__ float g_y[BDIM * HDIM];   // tanh(pre) activations
__device__ float g_z[BDIM * HDIM];   // tanh(expert out) activations (original sample order)
__device__ int g_perm[BDIM];
__device__ int g_counts[EDIM];
__device__ int g_cursor[EDIM];
__device__ int g_tile_expert[MAX_TILES];
__device__ int g_tile_row0[MAX_TILES];
__device__ int g_tile_nrows[MAX_TILES];

// ---------------- routing setup ----------------

__global__ void k_zero() {
    if (threadIdx.x < EDIM) g_counts[threadIdx.x] = 0;
}

__global__ void k_hist(const int* __restrict__ idx) {
    int b = blockIdx.x * blockDim.x + threadIdx.x;
    if (b < BDIM) atomicAdd(&g_counts[idx[b]], 1);
}

__global__ void k_build() {
    // single thread: prefix sum + tile table
    int off = 0, t = 0;
    for (int e = 0; e < EDIM; e++) {
        int n = g_counts[e];
        g_cursor[e] = off;
        int nt = (n + 127) >> 7;
        for (int i = 0; i < nt; i++) {
            g_tile_expert[t] = e;
            g_tile_row0[t] = off + (i << 7);
            int rem = n - (i << 7);
            g_tile_nrows[t] = rem < 128 ? rem : 128;
            t++;
        }
        off += n;
    }
    for (; t < MAX_TILES; t++) g_tile_expert[t] = -1;
}

__global__ void k_scatter(const int* __restrict__ idx) {
    int b = blockIdx.x * blockDim.x + threadIdx.x;
    if (b < BDIM) {
        int p = atomicAdd(&g_cursor[idx[b]], 1);
        g_perm[p] = b;  // order within expert arbitrary; result invariant
    }
}

// ---------------- GEMM: C = tanh(A @ W^T + bias) ----------------
// A: [M,K] row-major, W: [N,K] row-major. 128x128 block, BK=16, 256 threads,
// 8x8 per thread as 2x2 grid of 4x4 fragments (conflict-free LDS.128).

__global__ __launch_bounds__(256)
void gemm_tanh_k(const float* __restrict__ A, const float* __restrict__ W,
                 const float* __restrict__ bias, float* __restrict__ C,
                 int M, int N, int K) {
    __shared__ __align__(16) float As[16][128];
    __shared__ __align__(16) float Ws[16][128];
    int tid = threadIdx.x;
    int m0 = blockIdx.x * 128;
    int n0 = blockIdx.y * 128;
    int lr = tid >> 2;          // 0..63 (row for loads)
    int lk = (tid & 3) << 2;    // 0,4,8,12 (k for loads)
    int ty = tid >> 4;          // 0..15
    int tx = tid & 15;          // 0..15

    float acc[8][8];
#pragma unroll
    for (int i = 0; i < 8; i++)
#pragma unroll
        for (int j = 0; j < 8; j++) acc[i][j] = 0.f;

    const float* Ap = A + (size_t)m0 * K;
    const float* Wp = W + (size_t)n0 * K;

    for (int k0 = 0; k0 < K; k0 += 16) {
#pragma unroll
        for (int h = 0; h < 2; h++) {
            int r = lr + h * 64;
            float4 av = *(const float4*)(Ap + (size_t)r * K + k0 + lk);
            As[lk + 0][r] = av.x; As[lk + 1][r] = av.y;
            As[lk + 2][r] = av.z; As[lk + 3][r] = av.w;
            float4 wv = *(const float4*)(Wp + (size_t)r * K + k0 + lk);
            Ws[lk + 0][r] = wv.x; Ws[lk + 1][r] = wv.y;
            Ws[lk + 2][r] = wv.z; Ws[lk + 3][r] = wv.w;
        }
        __syncthreads();
#pragma unroll
        for (int k = 0; k < 16; k++) {
            float a[8], b[8];
            *(float4*)&a[0] = *(const float4*)&As[k][ty * 4];
            *(float4*)&a[4] = *(const float4*)&As[k][64 + ty * 4];
            *(float4*)&b[0] = *(const float4*)&Ws[k][tx * 4];
            *(float4*)&b[4] = *(const float4*)&Ws[k][64 + tx * 4];
#pragma unroll
            for (int i = 0; i < 8; i++)
#pragma unroll
                for (int j = 0; j < 8; j++)
                    acc[i][j] = fmaf(a[i], b[j], acc[i][j]);
        }
        __syncthreads();
    }

#pragma unroll
    for (int ih = 0; ih < 2; ih++) {
#pragma unroll
        for (int i = 0; i < 4; i++) {
            int row = m0 + ih * 64 + ty * 4 + i;
#pragma unroll
            for (int jh = 0; jh < 2; jh++) {
                int col = n0 + jh * 64 + tx * 4;
                float4 v;
                v.x = tanhf(acc[ih * 4 + i][jh * 4 + 0] + bias[col + 0]);
                v.y = tanhf(acc[ih * 4 + i][jh * 4 + 1] + bias[col + 1]);
                v.z = tanhf(acc[ih * 4 + i][jh * 4 + 2] + bias[col + 2]);
                v.w = tanhf(acc[ih * 4 + i][jh * 4 + 3] + bias[col + 3]);
                *(float4*)(C + (size_t)row * N + col) = v;
            }
        }
    }
}

// ---------------- Expert GEMM (gathered rows, scattered writes) ----------------
// z[b] = tanh(expert_w[e(b)] @ y[b] + expert_b[e(b)]) for rows of one expert tile.

__global__ __launch_bounds__(256)
void gemm_expert_k(const float* __restrict__ EW, const float* __restrict__ EB) {
    int e = g_tile_expert[blockIdx.x];
    if (e < 0) return;
    int row0 = g_tile_row0[blockIdx.x];
    int nrows = g_tile_nrows[blockIdx.x];
    int n0 = blockIdx.y * 128;

    __shared__ __align__(16) float As[16][128];
    __shared__ __align__(16) float Ws[16][128];
    __shared__ int permS[128];

    int tid = threadIdx.x;
    if (tid < 128) permS[tid] = (tid < nrows) ? g_perm[row0 + tid] : -1;
    __syncthreads();

    int lr = tid >> 2;
    int lk = (tid & 3) << 2;
    int ty = tid >> 4;
    int tx = tid & 15;

    float acc[8][8];
#pragma unroll
    for (int i = 0; i < 8; i++)
#pragma unroll
        for (int j = 0; j < 8; j++) acc[i][j] = 0.f;

    const float* Wp = EW + (size_t)e * HDIM * HDIM + (size_t)n0 * HDIM;

    for (int k0 = 0; k0 < HDIM; k0 += 16) {
#pragma unroll
        for (int h = 0; h < 2; h++) {
            int r = lr + h * 64;
            int pr = permS[r];
            float4 av = make_float4(0.f, 0.f, 0.f, 0.f);
            if (pr >= 0)
                av = *(const float4*)(g_y + (size_t)pr * HDIM + k0 + lk);
            As[lk + 0][r] = av.x; As[lk + 1][r] = av.y;
            As[lk + 2][r] = av.z; As[lk + 3][r] = av.w;
            float4 wv = *(const float4*)(Wp + (size_t)r * HDIM + k0 + lk);
            Ws[lk + 0][r] = wv.x; Ws[lk + 1][r] = wv.y;
            Ws[lk + 2][r] = wv.z; Ws[lk + 3][r] = wv.w;
        }
        __syncthreads();
#pragma unroll
        for (int k = 0; k < 16; k++) {
            float a[8], b[8];
            *(float4*)&a[0] = *(const float4*)&As[k][ty * 4];
            *(float4*)&a[4] = *(const float4*)&As[k][64 + ty * 4];
            *(float4*)&b[0] = *(const float4*)&Ws[k][tx * 4];
            *(float4*)&b[4] = *(const float4*)&Ws[k][64 + tx * 4];
#pragma unroll
            for (int i = 0; i < 8; i++)
#pragma unroll
                for (int j = 0; j < 8; j++)
                    acc[i][j] = fmaf(a[i], b[j], acc[i][j]);
        }
        __syncthreads();
    }

    const float* bias = EB + (size_t)e * HDIM;
#pragma unroll
    for (int ih = 0; ih < 2; ih++) {
#pragma unroll
        for (int i = 0; i < 4; i++) {
            int r = ih * 64 + ty * 4 + i;
            int pr = permS[r];
            if (pr < 0) continue;
#pragma unroll
            for (int jh = 0; jh < 2; jh++) {
                int col = n0 + jh * 64 + tx * 4;
                float4 v;
                v.x = tanhf(acc[ih * 4 + i][jh * 4 + 0] + bias[col + 0]);
                v.y = tanhf(acc[ih * 4 + i][jh * 4 + 1] + bias[col + 1]);
                v.z = tanhf(acc[ih * 4 + i][jh * 4 + 2] + bias[col + 2]);
                v.w = tanhf(acc[ih * 4 + i][jh * 4 + 3] + bias[col + 3]);
                *(float4*)(g_z + (size_t)pr * HDIM + col) = v;
            }
        }
    }
}

// ---------------- launch ----------------

extern "C" void kernel_launch(void* const* d_in, const int* in_sizes, int n_in,
                              void* d_out, int out_size) {
    const float* obs   = (const float*)d_in[0];
    const int*   swidx = (const int*)d_in[1];
    const float* pre_w = (const float*)d_in[2];
    const float* pre_b = (const float*)d_in[3];
    const float* ew    = (const float*)d_in[4];
    const float* eb    = (const float*)d_in[5];
    const float* pw    = (const float*)d_in[6];
    const float* pb    = (const float*)d_in[7];
    float* out = (float*)d_out;

    float *yp, *zp;
    cudaGetSymbolAddress((void**)&yp, g_y);
    cudaGetSymbolAddress((void**)&zp, g_z);

    // routing
    k_zero<<<1, 32>>>();
    k_hist<<<BDIM / 256, 256>>>(swidx);
    k_build<<<1, 1>>>();
    k_scatter<<<BDIM / 256, 256>>>(swidx);

    // pre: y = tanh(obs @ pre_w^T + pre_b)   [4096,2048], K=1024
    gemm_tanh_k<<<dim3(BDIM / 128, HDIM / 128), 256>>>(obs, pre_w, pre_b, yp,
                                                       BDIM, HDIM, INDIM);
    // experts (selected only): z = tanh(W_e @ y + b_e), K=2048
    gemm_expert_k<<<dim3(MAX_TILES, HDIM / 128), 256>>>(ew, eb);
    // post: out = tanh(z @ post_w^T + post_b)  [4096,1024], K=2048
    gemm_tanh_k<<<dim3(BDIM / 128, OUTDIM / 128), 256>>>(zp, pw, pb, out,
                                                         BDIM, OUTDIM, HDIM);
}

// round 3
// speedup vs baseline: 2.9566x; 2.9566x over previous
#include <cuda_runtime.h>
#include <cuda_bf16.h>
#include <cstdint>
#include <math.h>

#define BDIM 4096
#define INDIM 1024
#define HDIM 2048
#define OUTDIM 1024
#define EDIM 16
#define MAX_TILES 48

// ---------------- scratch (__device__ globals; no allocation allowed) ----------------
__device__ __nv_bfloat16 g_obs_h[BDIM * INDIM];
__device__ __nv_bfloat16 g_obs_l[BDIM * INDIM];
__device__ __nv_bfloat16 g_y_h[BDIM * HDIM];
__device__ __nv_bfloat16 g_y_l[BDIM * HDIM];
__device__ __nv_bfloat16 g_z_h[BDIM * HDIM];
__device__ __nv_bfloat16 g_z_l[BDIM * HDIM];
__device__ __nv_bfloat16 g_wpre_h[HDIM * INDIM];
__device__ __nv_bfloat16 g_wpre_l[HDIM * INDIM];
__device__ __nv_bfloat16 g_wexp_h[EDIM * HDIM * HDIM];
__device__ __nv_bfloat16 g_wexp_l[EDIM * HDIM * HDIM];
__device__ __nv_bfloat16 g_wpost_h[OUTDIM * HDIM];
__device__ __nv_bfloat16 g_wpost_l[OUTDIM * HDIM];
__device__ int g_perm[BDIM];
__device__ int g_counts[EDIM];
__device__ int g_cursor[EDIM];
__device__ int g_tile_expert[MAX_TILES];
__device__ int g_tile_row0[MAX_TILES];
__device__ int g_tile_nrows[MAX_TILES];

// ---------------- routing ----------------
__global__ void k_zero() {
    if (threadIdx.x < EDIM) g_counts[threadIdx.x] = 0;
}
__global__ void k_hist(const int* __restrict__ idx) {
    int b = blockIdx.x * blockDim.x + threadIdx.x;
    if (b < BDIM) atomicAdd(&g_counts[idx[b]], 1);
}
__global__ void k_build() {
    int off = 0, t = 0;
    for (int e = 0; e < EDIM; e++) {
        int n = g_counts[e];
        g_cursor[e] = off;
        int nt = (n + 127) >> 7;
        for (int i = 0; i < nt; i++) {
            g_tile_expert[t] = e;
            g_tile_row0[t] = off + (i << 7);
            int rem = n - (i << 7);
            g_tile_nrows[t] = rem < 128 ? rem : 128;
            t++;
        }
        off += n;
    }
    for (; t < MAX_TILES; t++) g_tile_expert[t] = -1;
}
__global__ void k_scatter(const int* __restrict__ idx) {
    int b = blockIdx.x * blockDim.x + threadIdx.x;
    if (b < BDIM) {
        int p = atomicAdd(&g_cursor[idx[b]], 1);
        g_perm[p] = b;
    }
}

// ---------------- fp32 -> bf16 hi/lo split ----------------
__global__ __launch_bounds__(256) void k_convert(const float* __restrict__ in,
                                                 __nv_bfloat16* __restrict__ h,
                                                 __nv_bfloat16* __restrict__ l, int n4) {
    int i = blockIdx.x * blockDim.x + threadIdx.x;
    if (i >= n4) return;
    float4 v = ((const float4*)in)[i];
    __nv_bfloat162 h0 = __floats2bfloat162_rn(v.x, v.y);
    __nv_bfloat162 h1 = __floats2bfloat162_rn(v.z, v.w);
    __nv_bfloat162 l0 = __floats2bfloat162_rn(v.x - __low2float(h0), v.y - __high2float(h0));
    __nv_bfloat162 l1 = __floats2bfloat162_rn(v.z - __low2float(h1), v.w - __high2float(h1));
    ((__nv_bfloat162*)h)[i * 2 + 0] = h0;
    ((__nv_bfloat162*)h)[i * 2 + 1] = h1;
    ((__nv_bfloat162*)l)[i * 2 + 0] = l0;
    ((__nv_bfloat162*)l)[i * 2 + 1] = l1;
}

// ---------------- PTX helpers ----------------
__device__ __forceinline__ uint32_t smem_to_u32(const void* p) {
    uint32_t a;
    asm("{ .reg .u64 t; cvta.to.shared.u64 t, %1; cvt.u32.u64 %0, t; }" : "=r"(a) : "l"(p));
    return a;
}

#define CP16(dst, src) \
    asm volatile("cp.async.cg.shared.global [%0], [%1], 16;" :: "r"(dst), "l"(src))
#define CP_COMMIT() asm volatile("cp.async.commit_group;" ::: "memory")
#define CP_WAIT1() asm volatile("cp.async.wait_group 1;" ::: "memory")

#define LDSM4(r, addr) \
    asm volatile("ldmatrix.sync.aligned.m8n8.x4.shared.b16 {%0,%1,%2,%3}, [%4];" \
        : "=r"((r)[0]), "=r"((r)[1]), "=r"((r)[2]), "=r"((r)[3]) : "r"(addr))

#define MMA(c, a, b0, b1) \
    asm volatile("mma.sync.aligned.m16n8k16.row.col.f32.bf16.bf16.f32 " \
        "{%0,%1,%2,%3}, {%4,%5,%6,%7}, {%8,%9}, {%0,%1,%2,%3};" \
        : "+f"((c)[0]), "+f"((c)[1]), "+f"((c)[2]), "+f"((c)[3]) \
        : "r"((a)[0]), "r"((a)[1]), "r"((a)[2]), "r"((a)[3]), "r"(b0), "r"(b1))

#define SWZ(off) ((off) ^ (((off) >> 3) & 0x70))

// ---------------- GEMM config ----------------
#define BM 128
#define BN 128
#define BK 64
#define STAGES 3
#define TILE_B 16384            // one 128x64 bf16 tile
#define STAGE_B (4 * TILE_B)    // Ah, Al, Bh, Bl
#define SM_STAGE0 1024
#define SMEM_TOTAL (SM_STAGE0 + STAGES * STAGE_B)   // 197632

// C[M,N] = tanh(A @ W^T + bias); A = Ah+Al, W = Wh+Wl (bf16 split, 3 MMA passes)
template <bool GATHER, bool SPLIT_OUT>
__global__ __launch_bounds__(256, 1) void gemm_mma(
    const __nv_bfloat16* __restrict__ Ah, const __nv_bfloat16* __restrict__ Al,
    const __nv_bfloat16* __restrict__ Wh, const __nv_bfloat16* __restrict__ Wl,
    const float* __restrict__ bias,
    float* __restrict__ Cf, __nv_bfloat16* __restrict__ Ch, __nv_bfloat16* __restrict__ Cl,
    int K, int ldc) {
    extern __shared__ char smem[];
    int tid = threadIdx.x, lane = tid & 31, wid = tid >> 5;
    int* permS = (int*)smem;

    int nrows = BM;
    if (GATHER) {
        int e = g_tile_expert[blockIdx.x];
        if (e < 0) return;
        nrows = g_tile_nrows[blockIdx.x];
        int row0 = g_tile_row0[blockIdx.x];
        Wh += (size_t)e * HDIM * HDIM;
        Wl += (size_t)e * HDIM * HDIM;
        bias += (size_t)e * HDIM;
        if (tid < BM) {
            int rr = tid < nrows ? tid : nrows - 1;
            permS[tid] = g_perm[row0 + rr];
        }
    } else {
        Ah += (size_t)blockIdx.x * BM * K;
        Al += (size_t)blockIdx.x * BM * K;
    }
    int n0 = blockIdx.y * BN;
    __syncthreads();

    uint32_t sb = smem_to_u32(smem);

    // cp.async geometry: 4 x 16B per thread per tile
    uint32_t swo[4];
    const __nv_bfloat16 *ah_src[4], *al_src[4], *bh_src[4], *bl_src[4];
#pragma unroll
    for (int i = 0; i < 4; i++) {
        int idx = tid + i * 256;
        int r = idx >> 3;          // 0..127
        int cb = (idx & 7) * 16;   // byte column within 128B row
        swo[i] = SWZ(r * 128 + cb);
        int ce = cb >> 1;          // element column
        int ar = GATHER ? permS[r] : r;
        ah_src[i] = Ah + (size_t)ar * K + ce;
        al_src[i] = Al + (size_t)ar * K + ce;
        bh_src[i] = Wh + (size_t)(n0 + r) * K + ce;
        bl_src[i] = Wl + (size_t)(n0 + r) * K + ce;
    }

    auto issue = [&](int stage, int kc) {
        uint32_t base = sb + SM_STAGE0 + stage * STAGE_B;
#pragma unroll
        for (int i = 0; i < 4; i++) {
            CP16(base + 0 * TILE_B + swo[i], ah_src[i] + kc);
            CP16(base + 1 * TILE_B + swo[i], al_src[i] + kc);
            CP16(base + 2 * TILE_B + swo[i], bh_src[i] + kc);
            CP16(base + 3 * TILE_B + swo[i], bl_src[i] + kc);
        }
    };

    int NC = K / BK;
    issue(0, 0);
    CP_COMMIT();
    issue(1, BK);
    CP_COMMIT();

    float acc[4][4][4];
#pragma unroll
    for (int m = 0; m < 4; m++)
#pragma unroll
        for (int n = 0; n < 4; n++)
#pragma unroll
            for (int q = 0; q < 4; q++) acc[m][n][q] = 0.f;

    int wm = wid >> 2;   // 0..1
    int wn = wid & 3;    // 0..3
    int arow = (lane & 7) + ((lane >> 3) & 1) * 8;
    int brow = (lane & 7) + ((lane >> 4) & 1) * 8;

    for (int c = 0; c < NC; c++) {
        CP_WAIT1();
        __syncthreads();
        if (c + 2 < NC) issue((c + 2) % STAGES, (c + 2) * BK);
        CP_COMMIT();
        uint32_t base = sb + SM_STAGE0 + (c % STAGES) * STAGE_B;
#pragma unroll
        for (int kk = 0; kk < 4; kk++) {
            int k0 = kk * 16;
            int acol = k0 + (lane >> 4) * 8;
            int bcol = k0 + ((lane >> 3) & 1) * 8;
            uint32_t ah[4][4], al[4][4];
#pragma unroll
            for (int m = 0; m < 4; m++) {
                uint32_t off = SWZ((wm * 64 + m * 16 + arow) * 128 + acol * 2);
                LDSM4(ah[m], base + 0 * TILE_B + off);
                LDSM4(al[m], base + 1 * TILE_B + off);
            }
            uint32_t bh[2][4], bl[2][4];
#pragma unroll
            for (int p = 0; p < 2; p++) {
                uint32_t off = SWZ((wn * 32 + p * 16 + brow) * 128 + bcol * 2);
                LDSM4(bh[p], base + 2 * TILE_B + off);
                LDSM4(bl[p], base + 3 * TILE_B + off);
            }
#pragma unroll
            for (int m = 0; m < 4; m++)
#pragma unroll
                for (int n = 0; n < 4; n++) {
                    uint32_t b0h = bh[n >> 1][(n & 1) * 2], b1h = bh[n >> 1][(n & 1) * 2 + 1];
                    uint32_t b0l = bl[n >> 1][(n & 1) * 2], b1l = bl[n >> 1][(n & 1) * 2 + 1];
                    MMA(acc[m][n], ah[m], b0h, b1h);
                    MMA(acc[m][n], al[m], b0h, b1h);
                    MMA(acc[m][n], ah[m], b0l, b1l);
                }
        }
    }

    // epilogue: bias + tanh, write fp32 or bf16 hi/lo split
    int g = lane >> 2, t4 = lane & 3;
#pragma unroll
    for (int m = 0; m < 4; m++) {
#pragma unroll
        for (int half = 0; half < 2; half++) {
            int rl = wm * 64 + m * 16 + g + half * 8;
            if (GATHER && rl >= nrows) continue;
            int grow = GATHER ? permS[rl] : blockIdx.x * BM + rl;
#pragma unroll
            for (int n = 0; n < 4; n++) {
                int col = n0 + wn * 32 + n * 8 + t4 * 2;
                float v0 = tanhf(acc[m][n][half * 2 + 0] + bias[col]);
                float v1 = tanhf(acc[m][n][half * 2 + 1] + bias[col + 1]);
                if (SPLIT_OUT) {
                    __nv_bfloat162 h = __floats2bfloat162_rn(v0, v1);
                    __nv_bfloat162 lo = __floats2bfloat162_rn(v0 - __low2float(h),
                                                              v1 - __high2float(h));
                    *(__nv_bfloat162*)(Ch + (size_t)grow * ldc + col) = h;
                    *(__nv_bfloat162*)(Cl + (size_t)grow * ldc + col) = lo;
                } else {
                    *(float2*)(Cf + (size_t)grow * ldc + col) = make_float2(v0, v1);
                }
            }
        }
    }
}

// ---------------- launch ----------------
extern "C" void kernel_launch(void* const* d_in, const int* in_sizes, int n_in,
                              void* d_out, int out_size) {
    const float* obs   = (const float*)d_in[0];
    const int*   swidx = (const int*)d_in[1];
    const float* pre_w = (const float*)d_in[2];
    const float* pre_b = (const float*)d_in[3];
    const float* ew    = (const float*)d_in[4];
    const float* eb    = (const float*)d_in[5];
    const float* pw    = (const float*)d_in[6];
    const float* pb    = (const float*)d_in[7];
    float* out = (float*)d_out;

    __nv_bfloat16 *obs_h, *obs_l, *y_h, *y_l, *z_h, *z_l;
    __nv_bfloat16 *wpre_h, *wpre_l, *wexp_h, *wexp_l, *wpost_h, *wpost_l;
    cudaGetSymbolAddress((void**)&obs_h, g_obs_h);
    cudaGetSymbolAddress((void**)&obs_l, g_obs_l);
    cudaGetSymbolAddress((void**)&y_h, g_y_h);
    cudaGetSymbolAddress((void**)&y_l, g_y_l);
    cudaGetSymbolAddress((void**)&z_h, g_z_h);
    cudaGetSymbolAddress((void**)&z_l, g_z_l);
    cudaGetSymbolAddress((void**)&wpre_h, g_wpre_h);
    cudaGetSymbolAddress((void**)&wpre_l, g_wpre_l);
    cudaGetSymbolAddress((void**)&wexp_h, g_wexp_h);
    cudaGetSymbolAddress((void**)&wexp_l, g_wexp_l);
    cudaGetSymbolAddress((void**)&wpost_h, g_wpost_h);
    cudaGetSymbolAddress((void**)&wpost_l, g_wpost_l);

    cudaFuncSetAttribute(gemm_mma<false, true>,
                         cudaFuncAttributeMaxDynamicSharedMemorySize, SMEM_TOTAL);
    cudaFuncSetAttribute(gemm_mma<true, true>,
                         cudaFuncAttributeMaxDynamicSharedMemorySize, SMEM_TOTAL);
    cudaFuncSetAttribute(gemm_mma<false, false>,
                         cudaFuncAttributeMaxDynamicSharedMemorySize, SMEM_TOTAL);

    // routing
    k_zero<<<1, 32>>>();
    k_hist<<<BDIM / 256, 256>>>(swidx);
    k_build<<<1, 1>>>();
    k_scatter<<<BDIM / 256, 256>>>(swidx);

    // bf16 hi/lo pre-splits
    {
        int n4;
        n4 = BDIM * INDIM / 4;
        k_convert<<<(n4 + 255) / 256, 256>>>(obs, obs_h, obs_l, n4);
        n4 = HDIM * INDIM / 4;
        k_convert<<<(n4 + 255) / 256, 256>>>(pre_w, wpre_h, wpre_l, n4);
        n4 = EDIM * HDIM * HDIM / 4;
        k_convert<<<(n4 + 255) / 256, 256>>>(ew, wexp_h, wexp_l, n4);
        n4 = OUTDIM * HDIM / 4;
        k_convert<<<(n4 + 255) / 256, 256>>>(pw, wpost_h, wpost_l, n4);
    }

    // pre: y = tanh(obs @ pre_w^T + pre_b): M=4096, N=2048, K=1024
    gemm_mma<false, true><<<dim3(BDIM / BM, HDIM / BN), 256, SMEM_TOTAL>>>(
        obs_h, obs_l, wpre_h, wpre_l, pre_b, nullptr, y_h, y_l, INDIM, HDIM);
    // experts: z = tanh(W_e @ y + b_e): gathered rows, N=2048, K=2048
    gemm_mma<true, true><<<dim3(MAX_TILES, HDIM / BN), 256, SMEM_TOTAL>>>(
        y_h, y_l, wexp_h, wexp_l, eb, nullptr, z_h, z_l, HDIM, HDIM);
    // post: out = tanh(z @ post_w^T + post_b): M=4096, N=1024, K=2048
    gemm_mma<false, false><<<dim3(BDIM / BM, OUTDIM / BN), 256, SMEM_TOTAL>>>(
        z_h, z_l, wpost_h, wpost_l, pb, out, nullptr, nullptr, HDIM, OUTDIM);
}

// round 4
// speedup vs baseline: 3.9141x; 1.3238x over previous
#include <cuda_runtime.h>
#include <cuda_fp16.h>
#include <cstdint>
#include <math.h>

#define BDIM 4096
#define INDIM 1024
#define HDIM 2048
#define OUTDIM 1024
#define EDIM 16
#define MAX_TILES 48

// ---------------- scratch (__device__ globals; no allocation allowed) ----------------
__device__ __half g_obs_h[BDIM * INDIM];
__device__ __half g_obs_l[BDIM * INDIM];
__device__ __half g_y_h[BDIM * HDIM];
__device__ __half g_y_l[BDIM * HDIM];
__device__ __half g_z_h[BDIM * HDIM];
__device__ __half g_z_l[BDIM * HDIM];
__device__ __half g_wpre[HDIM * INDIM];
__device__ __half g_wexp[EDIM * HDIM * HDIM];
__device__ __half g_wpost[OUTDIM * HDIM];
__device__ int g_perm[BDIM];
__device__ int g_counts[EDIM];
__device__ int g_cursor[EDIM];
__device__ int g_tile_expert[MAX_TILES];
__device__ int g_tile_row0[MAX_TILES];
__device__ int g_tile_nrows[MAX_TILES];

// ---------------- routing ----------------
__global__ void k_zero() {
    if (threadIdx.x < EDIM) g_counts[threadIdx.x] = 0;
}
__global__ void k_hist(const int* __restrict__ idx) {
    int b = blockIdx.x * blockDim.x + threadIdx.x;
    if (b < BDIM) atomicAdd(&g_counts[idx[b]], 1);
}
__global__ void k_build() {
    int off = 0, t = 0;
    for (int e = 0; e < EDIM; e++) {
        int n = g_counts[e];
        g_cursor[e] = off;
        int nt = (n + 127) >> 7;
        for (int i = 0; i < nt; i++) {
            g_tile_expert[t] = e;
            g_tile_row0[t] = off + (i << 7);
            int rem = n - (i << 7);
            g_tile_nrows[t] = rem < 128 ? rem : 128;
            t++;
        }
        off += n;
    }
    for (; t < MAX_TILES; t++) g_tile_expert[t] = -1;
}
__global__ void k_scatter(const int* __restrict__ idx) {
    int b = blockIdx.x * blockDim.x + threadIdx.x;
    if (b < BDIM) {
        int p = atomicAdd(&g_cursor[idx[b]], 1);
        g_perm[p] = b;
    }
}

// ---------------- converts ----------------
// fp32 -> fp16 hi/lo split (activations)
__global__ __launch_bounds__(256) void k_split_hl(const float* __restrict__ in,
                                                  __half* __restrict__ h,
                                                  __half* __restrict__ l, int n4) {
    int i = blockIdx.x * blockDim.x + threadIdx.x;
    if (i >= n4) return;
    float4 v = ((const float4*)in)[i];
    __half2 h0 = __floats2half2_rn(v.x, v.y);
    __half2 h1 = __floats2half2_rn(v.z, v.w);
    __half2 l0 = __floats2half2_rn(v.x - __low2float(h0), v.y - __high2float(h0));
    __half2 l1 = __floats2half2_rn(v.z - __low2float(h1), v.w - __high2float(h1));
    ((__half2*)h)[i * 2 + 0] = h0;
    ((__half2*)h)[i * 2 + 1] = h1;
    ((__half2*)l)[i * 2 + 0] = l0;
    ((__half2*)l)[i * 2 + 1] = l1;
}
// fp32 -> fp16 (weights, single)
__global__ __launch_bounds__(256) void k_tohalf(const float* __restrict__ in,
                                                __half* __restrict__ h, int n4) {
    int i = blockIdx.x * blockDim.x + threadIdx.x;
    if (i >= n4) return;
    float4 v = ((const float4*)in)[i];
    ((__half2*)h)[i * 2 + 0] = __floats2half2_rn(v.x, v.y);
    ((__half2*)h)[i * 2 + 1] = __floats2half2_rn(v.z, v.w);
}

// ---------------- PTX helpers ----------------
__device__ __forceinline__ uint32_t smem_to_u32(const void* p) {
    uint32_t a;
    asm("{ .reg .u64 t; cvta.to.shared.u64 t, %1; cvt.u32.u64 %0, t; }" : "=r"(a) : "l"(p));
    return a;
}
#define CP16(dst, src) \
    asm volatile("cp.async.cg.shared.global [%0], [%1], 16;" :: "r"(dst), "l"(src))
#define CP_COMMIT() asm volatile("cp.async.commit_group;" ::: "memory")
#define CP_WAIT1() asm volatile("cp.async.wait_group 1;" ::: "memory")
#define LDSM4(r, addr) \
    asm volatile("ldmatrix.sync.aligned.m8n8.x4.shared.b16 {%0,%1,%2,%3}, [%4];" \
        : "=r"((r)[0]), "=r"((r)[1]), "=r"((r)[2]), "=r"((r)[3]) : "r"(addr))
#define MMA(c, a, b0, b1) \
    asm volatile("mma.sync.aligned.m16n8k16.row.col.f32.f16.f16.f32 " \
        "{%0,%1,%2,%3}, {%4,%5,%6,%7}, {%8,%9}, {%0,%1,%2,%3};" \
        : "+f"((c)[0]), "+f"((c)[1]), "+f"((c)[2]), "+f"((c)[3]) \
        : "r"((a)[0]), "r"((a)[1]), "r"((a)[2]), "r"((a)[3]), "r"(b0), "r"(b1))
#define SWZ(off) ((off) ^ (((off) >> 3) & 0x70))

// ---------------- GEMM config ----------------
#define BM 128
#define BN 256
#define BK 64
#define STAGES 3
#define A_TILE_B 16384          // 128x64 fp16
#define B_TILE_B 32768          // 256x64 fp16
#define STAGE_B (2 * A_TILE_B + B_TILE_B)   // Ah, Al, Bh = 64KB
#define SM_STAGE0 1024
#define SMEM_TOTAL (SM_STAGE0 + STAGES * STAGE_B)   // 197632

// C[M,N] = tanh(A @ W^T + bias); A = Ah+Al fp16 pair, W = fp16 (2 MMA passes)
template <bool GATHER, bool SPLIT_OUT>
__global__ __launch_bounds__(256, 1) void gemm_mma(
    const __half* __restrict__ Ah, const __half* __restrict__ Al,
    const __half* __restrict__ Wh, const float* __restrict__ bias,
    float* __restrict__ Cf, __half* __restrict__ Ch, __half* __restrict__ Cl,
    int K, int ldc) {
    extern __shared__ char smem[];
    int tid = threadIdx.x, lane = tid & 31, wid = tid >> 5;
    int* permS = (int*)smem;

    int nrows = BM;
    if (GATHER) {
        int e = g_tile_expert[blockIdx.x];
        if (e < 0) return;
        nrows = g_tile_nrows[blockIdx.x];
        int row0 = g_tile_row0[blockIdx.x];
        Wh += (size_t)e * HDIM * HDIM;
        bias += (size_t)e * HDIM;
        if (tid < BM) {
            int rr = tid < nrows ? tid : nrows - 1;
            permS[tid] = g_perm[row0 + rr];
        }
    } else {
        Ah += (size_t)blockIdx.x * BM * K;
        Al += (size_t)blockIdx.x * BM * K;
    }
    int n0 = blockIdx.y * BN;
    __syncthreads();

    uint32_t sb = smem_to_u32(smem);

    // cp.async geometry: A tiles 4 x 16B/thread each, B tile 8 x 16B/thread
    uint32_t swa[4], swb[8];
    const __half *ah_src[4], *al_src[4], *bh_src[8];
#pragma unroll
    for (int i = 0; i < 4; i++) {
        int idx = tid + i * 256;
        int r = idx >> 3;
        int cb = (idx & 7) * 16;
        swa[i] = SWZ(r * 128 + cb);
        int ce = cb >> 1;
        int ar = GATHER ? permS[r] : r;
        ah_src[i] = Ah + (size_t)ar * K + ce;
        al_src[i] = Al + (size_t)ar * K + ce;
    }
#pragma unroll
    for (int i = 0; i < 8; i++) {
        int idx = tid + i * 256;
        int r = idx >> 3;          // 0..255
        int cb = (idx & 7) * 16;
        swb[i] = SWZ(r * 128 + cb);
        bh_src[i] = Wh + (size_t)(n0 + r) * K + (cb >> 1);
    }

    auto issue = [&](int stage, int kc) {
        uint32_t base = sb + SM_STAGE0 + stage * STAGE_B;
#pragma unroll
        for (int i = 0; i < 4; i++) {
            CP16(base + swa[i], ah_src[i] + kc);
            CP16(base + A_TILE_B + swa[i], al_src[i] + kc);
        }
#pragma unroll
        for (int i = 0; i < 8; i++)
            CP16(base + 2 * A_TILE_B + swb[i], bh_src[i] + kc);
    };

    int NC = K / BK;
    issue(0, 0);
    CP_COMMIT();
    issue(1, BK);
    CP_COMMIT();

    float acc[4][8][4];
#pragma unroll
    for (int m = 0; m < 4; m++)
#pragma unroll
        for (int n = 0; n < 8; n++)
#pragma unroll
            for (int q = 0; q < 4; q++) acc[m][n][q] = 0.f;

    int wm = wid >> 2;   // 0..1 : 64-row half
    int wn = wid & 3;    // 0..3 : 64-col group
    int arow = (lane & 7) + ((lane >> 3) & 1) * 8;
    int brow = (lane & 7) + ((lane >> 4) & 1) * 8;

    for (int c = 0; c < NC; c++) {
        CP_WAIT1();
        __syncthreads();
        if (c + 2 < NC) issue((c + 2) % STAGES, (c + 2) * BK);
        CP_COMMIT();
        uint32_t base = sb + SM_STAGE0 + (c % STAGES) * STAGE_B;
#pragma unroll
        for (int kk = 0; kk < 4; kk++) {
            int k0 = kk * 16;
            int acol = k0 + (lane >> 4) * 8;
            int bcol = k0 + ((lane >> 3) & 1) * 8;
            uint32_t ah[4][4], al[4][4];
#pragma unroll
            for (int m = 0; m < 4; m++) {
                uint32_t off = SWZ((wm * 64 + m * 16 + arow) * 128 + acol * 2);
                LDSM4(ah[m], base + off);
                LDSM4(al[m], base + A_TILE_B + off);
            }
            uint32_t bh[4][4];
#pragma unroll
            for (int p = 0; p < 4; p++) {
                uint32_t off = SWZ((wn * 64 + p * 16 + brow) * 128 + bcol * 2);
                LDSM4(bh[p], base + 2 * A_TILE_B + off);
            }
#pragma unroll
            for (int m = 0; m < 4; m++)
#pragma unroll
                for (int n = 0; n < 8; n++) {
                    uint32_t b0 = bh[n >> 1][(n & 1) * 2];
                    uint32_t b1 = bh[n >> 1][(n & 1) * 2 + 1];
                    MMA(acc[m][n], ah[m], b0, b1);
                    MMA(acc[m][n], al[m], b0, b1);
                }
        }
    }

    // epilogue: bias + tanh, write fp32 or fp16 hi/lo split
    int g = lane >> 2, t4 = lane & 3;
#pragma unroll
    for (int m = 0; m < 4; m++) {
#pragma unroll
        for (int half_ = 0; half_ < 2; half_++) {
            int rl = wm * 64 + m * 16 + g + half_ * 8;
            if (GATHER && rl >= nrows) continue;
            int grow = GATHER ? permS[rl] : blockIdx.x * BM + rl;
#pragma unroll
            for (int n = 0; n < 8; n++) {
                int col = n0 + wn * 64 + n * 8 + t4 * 2;
                float v0 = tanhf(acc[m][n][half_ * 2 + 0] + bias[col]);
                float v1 = tanhf(acc[m][n][half_ * 2 + 1] + bias[col + 1]);
                if (SPLIT_OUT) {
                    __half2 h = __floats2half2_rn(v0, v1);
                    __half2 lo = __floats2half2_rn(v0 - __low2float(h),
                                                   v1 - __high2float(h));
                    *(__half2*)(Ch + (size_t)grow * ldc + col) = h;
                    *(__half2*)(Cl + (size_t)grow * ldc + col) = lo;
                } else {
                    *(float2*)(Cf + (size_t)grow * ldc + col) = make_float2(v0, v1);
                }
            }
        }
    }
}

// ---------------- launch ----------------
extern "C" void kernel_launch(void* const* d_in, const int* in_sizes, int n_in,
                              void* d_out, int out_size) {
    const float* obs   = (const float*)d_in[0];
    const int*   swidx = (const int*)d_in[1];
    const float* pre_w = (const float*)d_in[2];
    const float* pre_b = (const float*)d_in[3];
    const float* ew    = (const float*)d_in[4];
    const float* eb    = (const float*)d_in[5];
    const float* pw    = (const float*)d_in[6];
    const float* pb    = (const float*)d_in[7];
    float* out = (float*)d_out;

    __half *obs_h, *obs_l, *y_h, *y_l, *z_h, *z_l, *wpre, *wexp, *wpost;
    cudaGetSymbolAddress((void**)&obs_h, g_obs_h);
    cudaGetSymbolAddress((void**)&obs_l, g_obs_l);
    cudaGetSymbolAddress((void**)&y_h, g_y_h);
    cudaGetSymbolAddress((void**)&y_l, g_y_l);
    cudaGetSymbolAddress((void**)&z_h, g_z_h);
    cudaGetSymbolAddress((void**)&z_l, g_z_l);
    cudaGetSymbolAddress((void**)&wpre, g_wpre);
    cudaGetSymbolAddress((void**)&wexp, g_wexp);
    cudaGetSymbolAddress((void**)&wpost, g_wpost);

    cudaFuncSetAttribute(gemm_mma<false, true>,
                         cudaFuncAttributeMaxDynamicSharedMemorySize, SMEM_TOTAL);
    cudaFuncSetAttribute(gemm_mma<true, true>,
                         cudaFuncAttributeMaxDynamicSharedMemorySize, SMEM_TOTAL);
    cudaFuncSetAttribute(gemm_mma<false, false>,
                         cudaFuncAttributeMaxDynamicSharedMemorySize, SMEM_TOTAL);

    // routing
    k_zero<<<1, 32>>>();
    k_hist<<<BDIM / 256, 256>>>(swidx);
    k_build<<<1, 1>>>();
    k_scatter<<<BDIM / 256, 256>>>(swidx);

    // converts
    {
        int n4 = BDIM * INDIM / 4;
        k_split_hl<<<(n4 + 255) / 256, 256>>>(obs, obs_h, obs_l, n4);
        n4 = HDIM * INDIM / 4;
        k_tohalf<<<(n4 + 255) / 256, 256>>>(pre_w, wpre, n4);
        n4 = EDIM * HDIM * HDIM / 4;
        k_tohalf<<<(n4 + 255) / 256, 256>>>(ew, wexp, n4);
        n4 = OUTDIM * HDIM / 4;
        k_tohalf<<<(n4 + 255) / 256, 256>>>(pw, wpost, n4);
    }

    // pre: y = tanh(obs @ pre_w^T + pre_b): M=4096, N=2048, K=1024
    gemm_mma<false, true><<<dim3(BDIM / BM, HDIM / BN), 256, SMEM_TOTAL>>>(
        obs_h, obs_l, wpre, pre_b, nullptr, y_h, y_l, INDIM, HDIM);
    // experts: z = tanh(W_e @ y + b_e): gathered rows, N=2048, K=2048
    gemm_mma<true, true><<<dim3(MAX_TILES, HDIM / BN), 256, SMEM_TOTAL>>>(
        y_h, y_l, wexp, eb, nullptr, z_h, z_l, HDIM, HDIM);
    // post: out = tanh(z @ post_w^T + post_b): M=4096, N=1024, K=2048
    gemm_mma<false, false><<<dim3(BDIM / BM, OUTDIM / BN), 256, SMEM_TOTAL>>>(
        z_h, z_l, wpost, pb, out, nullptr, nullptr, HDIM, OUTDIM);
}

// round 5
// speedup vs baseline: 3.9974x; 1.0213x over previous
#include <cuda_runtime.h>
#include <cuda_fp16.h>
#include <cstdint>
#include <math.h>

#define BDIM 4096
#define INDIM 1024
#define HDIM 2048
#define OUTDIM 1024
#define EDIM 16
#define MAX_TILES 48

// ---------------- scratch (__device__ globals; no allocation allowed) ----------------
__device__ __half g_obs_h[BDIM * INDIM];
__device__ __half g_obs_l[BDIM * INDIM];
__device__ __half g_y_h[BDIM * HDIM];
__device__ __half g_y_l[BDIM * HDIM];
__device__ __half g_z_h[BDIM * HDIM];
__device__ __half g_z_l[BDIM * HDIM];
__device__ __half g_wpre[HDIM * INDIM];
__device__ __half g_wexp[EDIM * HDIM * HDIM];
__device__ __half g_wpost[OUTDIM * HDIM];
__device__ int g_perm[BDIM];
__device__ int g_counts[EDIM];
__device__ int g_cursor[EDIM];
__device__ int g_tile_expert[MAX_TILES];
__device__ int g_tile_row0[MAX_TILES];
__device__ int g_tile_nrows[MAX_TILES];

// ---------------- routing ----------------
__global__ void k_zero() {
    if (threadIdx.x < EDIM) g_counts[threadIdx.x] = 0;
}
__global__ void k_hist(const int* __restrict__ idx) {
    int b = blockIdx.x * blockDim.x + threadIdx.x;
    if (b < BDIM) atomicAdd(&g_counts[idx[b]], 1);
}
__global__ void k_build() {
    int off = 0, t = 0;
    for (int e = 0; e < EDIM; e++) {
        int n = g_counts[e];
        g_cursor[e] = off;
        int nt = (n + 127) >> 7;
        for (int i = 0; i < nt; i++) {
            g_tile_expert[t] = e;
            g_tile_row0[t] = off + (i << 7);
            int rem = n - (i << 7);
            g_tile_nrows[t] = rem < 128 ? rem : 128;
            t++;
        }
        off += n;
    }
    for (; t < MAX_TILES; t++) g_tile_expert[t] = -1;
}
__global__ void k_scatter(const int* __restrict__ idx) {
    int b = blockIdx.x * blockDim.x + threadIdx.x;
    if (b < BDIM) {
        int p = atomicAdd(&g_cursor[idx[b]], 1);
        g_perm[p] = b;
    }
}

// ---------------- converts ----------------
__global__ __launch_bounds__(256) void k_split_hl(const float* __restrict__ in,
                                                  __half* __restrict__ h,
                                                  __half* __restrict__ l, int n4) {
    int i = blockIdx.x * blockDim.x + threadIdx.x;
    if (i >= n4) return;
    float4 v = ((const float4*)in)[i];
    __half2 h0 = __floats2half2_rn(v.x, v.y);
    __half2 h1 = __floats2half2_rn(v.z, v.w);
    __half2 l0 = __floats2half2_rn(v.x - __low2float(h0), v.y - __high2float(h0));
    __half2 l1 = __floats2half2_rn(v.z - __low2float(h1), v.w - __high2float(h1));
    ((__half2*)h)[i * 2 + 0] = h0;
    ((__half2*)h)[i * 2 + 1] = h1;
    ((__half2*)l)[i * 2 + 0] = l0;
    ((__half2*)l)[i * 2 + 1] = l1;
}
__global__ __launch_bounds__(256) void k_tohalf(const float* __restrict__ in,
                                                __half* __restrict__ h, int n4) {
    int i = blockIdx.x * blockDim.x + threadIdx.x;
    if (i >= n4) return;
    float4 v = ((const float4*)in)[i];
    ((__half2*)h)[i * 2 + 0] = __floats2half2_rn(v.x, v.y);
    ((__half2*)h)[i * 2 + 1] = __floats2half2_rn(v.z, v.w);
}

// ---------------- PTX helpers ----------------
__device__ __forceinline__ uint32_t smem_to_u32(const void* p) {
    uint32_t a;
    asm("{ .reg .u64 t; cvta.to.shared.u64 t, %1; cvt.u32.u64 %0, t; }" : "=r"(a) : "l"(p));
    return a;
}
#define CP16(dst, src) \
    asm volatile("cp.async.cg.shared.global [%0], [%1], 16;" :: "r"(dst), "l"(src))
#define CP_COMMIT() asm volatile("cp.async.commit_group;" ::: "memory")
#define CP_WAIT1() asm volatile("cp.async.wait_group 1;" ::: "memory")
#define LDSM4(r, addr) \
    asm volatile("ldmatrix.sync.aligned.m8n8.x4.shared.b16 {%0,%1,%2,%3}, [%4];" \
        : "=r"((r)[0]), "=r"((r)[1]), "=r"((r)[2]), "=r"((r)[3]) : "r"(addr))
#define MMA(c, a, b0, b1) \
    asm volatile("mma.sync.aligned.m16n8k16.row.col.f32.f16.f16.f32 " \
        "{%0,%1,%2,%3}, {%4,%5,%6,%7}, {%8,%9}, {%0,%1,%2,%3};" \
        : "+f"((c)[0]), "+f"((c)[1]), "+f"((c)[2]), "+f"((c)[3]) \
        : "r"((a)[0]), "r"((a)[1]), "r"((a)[2]), "r"((a)[3]), "r"(b0), "r"(b1))
#define SWZ(off) ((off) ^ (((off) >> 3) & 0x70))

// ---------------- GEMM config ----------------
#define BM 128
#define BN 256
#define BK 64
#define STAGES 3
#define A_TILE_B 16384
#define B_TILE_B 32768
#define STAGE_B (2 * A_TILE_B + B_TILE_B)
#define SM_STAGE0 1024
#define SMEM_TOTAL (SM_STAGE0 + STAGES * STAGE_B)   // 197632

// C[M,N] = tanh(A @ W^T + bias); A = Ah+Al fp16 pair, W = fp16 (2 MMA passes)
// grid: x = N-block (L2 A-reuse within a wave), y = M-tile
template <bool GATHER, bool SPLIT_OUT>
__global__ __launch_bounds__(256, 1) void gemm_mma(
    const __half* __restrict__ Ah, const __half* __restrict__ Al,
    const __half* __restrict__ Wh, const float* __restrict__ bias,
    float* __restrict__ Cf, __half* __restrict__ Ch, __half* __restrict__ Cl,
    int K, int ldc) {
    extern __shared__ char smem[];
    int tid = threadIdx.x, lane = tid & 31, wid = tid >> 5;
    int* permS = (int*)smem;

    int nrows = BM;
    if (GATHER) {
        int e = g_tile_expert[blockIdx.y];
        if (e < 0) return;
        nrows = g_tile_nrows[blockIdx.y];
        int row0 = g_tile_row0[blockIdx.y];
        Wh += (size_t)e * HDIM * HDIM;
        bias += (size_t)e * HDIM;
        if (tid < BM) {
            int rr = tid < nrows ? tid : nrows - 1;
            permS[tid] = g_perm[row0 + rr];
        }
    } else {
        Ah += (size_t)blockIdx.y * BM * K;
        Al += (size_t)blockIdx.y * BM * K;
    }
    int n0 = blockIdx.x * BN;
    __syncthreads();

    uint32_t sb = smem_to_u32(smem);

    uint32_t swa[4], swb[8];
    const __half *ah_src[4], *al_src[4], *bh_src[8];
#pragma unroll
    for (int i = 0; i < 4; i++) {
        int idx = tid + i * 256;
        int r = idx >> 3;
        int cb = (idx & 7) * 16;
        swa[i] = SWZ(r * 128 + cb);
        int ce = cb >> 1;
        int ar = GATHER ? permS[r] : r;
        ah_src[i] = Ah + (size_t)ar * K + ce;
        al_src[i] = Al + (size_t)ar * K + ce;
    }
#pragma unroll
    for (int i = 0; i < 8; i++) {
        int idx = tid + i * 256;
        int r = idx >> 3;
        int cb = (idx & 7) * 16;
        swb[i] = SWZ(r * 128 + cb);
        bh_src[i] = Wh + (size_t)(n0 + r) * K + (cb >> 1);
    }

    auto issue = [&](int stage, int kc) {
        uint32_t base = sb + SM_STAGE0 + stage * STAGE_B;
#pragma unroll
        for (int i = 0; i < 4; i++) {
            CP16(base + swa[i], ah_src[i] + kc);
            CP16(base + A_TILE_B + swa[i], al_src[i] + kc);
        }
#pragma unroll
        for (int i = 0; i < 8; i++)
            CP16(base + 2 * A_TILE_B + swb[i], bh_src[i] + kc);
    };

    int NC = K / BK;
    issue(0, 0);
    CP_COMMIT();
    issue(1, BK);
    CP_COMMIT();

    float acc[4][8][4];
#pragma unroll
    for (int m = 0; m < 4; m++)
#pragma unroll
        for (int n = 0; n < 8; n++)
#pragma unroll
            for (int q = 0; q < 4; q++) acc[m][n][q] = 0.f;

    int wm = wid >> 2;
    int wn = wid & 3;
    int arow = (lane & 7) + ((lane >> 3) & 1) * 8;
    int brow = (lane & 7) + ((lane >> 4) & 1) * 8;

    for (int c = 0; c < NC; c++) {
        CP_WAIT1();
        __syncthreads();
        if (c + 2 < NC) issue((c + 2) % STAGES, (c + 2) * BK);
        CP_COMMIT();
        uint32_t base = sb + SM_STAGE0 + (c % STAGES) * STAGE_B;
#pragma unroll
        for (int kk = 0; kk < 4; kk++) {
            int k0 = kk * 16;
            int acol = k0 + (lane >> 4) * 8;
            int bcol = k0 + ((lane >> 3) & 1) * 8;
            uint32_t ah[4][4], al[4][4];
#pragma unroll
            for (int m = 0; m < 4; m++) {
                uint32_t off = SWZ((wm * 64 + m * 16 + arow) * 128 + acol * 2);
                LDSM4(ah[m], base + off);
                LDSM4(al[m], base + A_TILE_B + off);
            }
            uint32_t bh[4][4];
#pragma unroll
            for (int p = 0; p < 4; p++) {
                uint32_t off = SWZ((wn * 64 + p * 16 + brow) * 128 + bcol * 2);
                LDSM4(bh[p], base + 2 * A_TILE_B + off);
            }
#pragma unroll
            for (int m = 0; m < 4; m++)
#pragma unroll
                for (int n = 0; n < 8; n++) {
                    uint32_t b0 = bh[n >> 1][(n & 1) * 2];
                    uint32_t b1 = bh[n >> 1][(n & 1) * 2 + 1];
                    MMA(acc[m][n], ah[m], b0, b1);
                    MMA(acc[m][n], al[m], b0, b1);
                }
        }
    }

    int g = lane >> 2, t4 = lane & 3;
#pragma unroll
    for (int m = 0; m < 4; m++) {
#pragma unroll
        for (int half_ = 0; half_ < 2; half_++) {
            int rl = wm * 64 + m * 16 + g + half_ * 8;
            if (GATHER && rl >= nrows) continue;
            int grow = GATHER ? permS[rl] : blockIdx.y * BM + rl;
#pragma unroll
            for (int n = 0; n < 8; n++) {
                int col = n0 + wn * 64 + n * 8 + t4 * 2;
                float v0 = tanhf(acc[m][n][half_ * 2 + 0] + bias[col]);
                float v1 = tanhf(acc[m][n][half_ * 2 + 1] + bias[col + 1]);
                if (SPLIT_OUT) {
                    __half2 h = __floats2half2_rn(v0, v1);
                    __half2 lo = __floats2half2_rn(v0 - __low2float(h),
                                                   v1 - __high2float(h));
                    *(__half2*)(Ch + (size_t)grow * ldc + col) = h;
                    *(__half2*)(Cl + (size_t)grow * ldc + col) = lo;
                } else {
                    *(float2*)(Cf + (size_t)grow * ldc + col) = make_float2(v0, v1);
                }
            }
        }
    }
}

// ---------------- launch ----------------
extern "C" void kernel_launch(void* const* d_in, const int* in_sizes, int n_in,
                              void* d_out, int out_size) {
    const float* obs   = (const float*)d_in[0];
    const int*   swidx = (const int*)d_in[1];
    const float* pre_w = (const float*)d_in[2];
    const float* pre_b = (const float*)d_in[3];
    const float* ew    = (const float*)d_in[4];
    const float* eb    = (const float*)d_in[5];
    const float* pw    = (const float*)d_in[6];
    const float* pb    = (const float*)d_in[7];
    float* out = (float*)d_out;

    __half *obs_h, *obs_l, *y_h, *y_l, *z_h, *z_l, *wpre, *wexp, *wpost;
    cudaGetSymbolAddress((void**)&obs_h, g_obs_h);
    cudaGetSymbolAddress((void**)&obs_l, g_obs_l);
    cudaGetSymbolAddress((void**)&y_h, g_y_h);
    cudaGetSymbolAddress((void**)&y_l, g_y_l);
    cudaGetSymbolAddress((void**)&z_h, g_z_h);
    cudaGetSymbolAddress((void**)&z_l, g_z_l);
    cudaGetSymbolAddress((void**)&wpre, g_wpre);
    cudaGetSymbolAddress((void**)&wexp, g_wexp);
    cudaGetSymbolAddress((void**)&wpost, g_wpost);

    static cudaStream_t sR = nullptr, sC = nullptr;
    static cudaEvent_t evFork, evRoute, evWexp, evWpost;
    if (!sR) {
        cudaStreamCreateWithFlags(&sR, cudaStreamNonBlocking);
        cudaStreamCreateWithFlags(&sC, cudaStreamNonBlocking);
        cudaEventCreateWithFlags(&evFork, cudaEventDisableTiming);
        cudaEventCreateWithFlags(&evRoute, cudaEventDisableTiming);
        cudaEventCreateWithFlags(&evWexp, cudaEventDisableTiming);
        cudaEventCreateWithFlags(&evWpost, cudaEventDisableTiming);
        cudaFuncSetAttribute(gemm_mma<false, true>,
                             cudaFuncAttributeMaxDynamicSharedMemorySize, SMEM_TOTAL);
        cudaFuncSetAttribute(gemm_mma<true, true>,
                             cudaFuncAttributeMaxDynamicSharedMemorySize, SMEM_TOTAL);
        cudaFuncSetAttribute(gemm_mma<false, false>,
                             cudaFuncAttributeMaxDynamicSharedMemorySize, SMEM_TOTAL);
    }

    // fork side streams off the main (capture) stream
    cudaEventRecord(evFork, 0);
    cudaStreamWaitEvent(sR, evFork, 0);
    cudaStreamWaitEvent(sC, evFork, 0);

    // routing chain on sR (needed only by expert GEMM)
    k_zero<<<1, 32, 0, sR>>>();
    k_hist<<<BDIM / 256, 256, 0, sR>>>(swidx);
    k_build<<<1, 1, 0, sR>>>();
    k_scatter<<<BDIM / 256, 256, 0, sR>>>(swidx);
    cudaEventRecord(evRoute, sR);

    // big weight converts on sC (overlap with pre GEMM)
    {
        int n4 = EDIM * HDIM * HDIM / 4;
        k_tohalf<<<(n4 + 255) / 256, 256, 0, sC>>>(ew, wexp, n4);
        cudaEventRecord(evWexp, sC);
        n4 = OUTDIM * HDIM / 4;
        k_tohalf<<<(n4 + 255) / 256, 256, 0, sC>>>(pw, wpost, n4);
        cudaEventRecord(evWpost, sC);
    }

    // critical path: obs split + wpre convert -> pre GEMM
    {
        int n4 = BDIM * INDIM / 4;
        k_split_hl<<<(n4 + 255) / 256, 256>>>(obs, obs_h, obs_l, n4);
        n4 = HDIM * INDIM / 4;
        k_tohalf<<<(n4 + 255) / 256, 256>>>(pre_w, wpre, n4);
    }
    // pre: y = tanh(obs @ pre_w^T + pre_b): M=4096, N=2048, K=1024
    gemm_mma<false, true><<<dim3(HDIM / BN, BDIM / BM), 256, SMEM_TOTAL>>>(
        obs_h, obs_l, wpre, pre_b, nullptr, y_h, y_l, INDIM, HDIM);

    // join routing + expert weights, then expert GEMM
    cudaStreamWaitEvent(0, evRoute, 0);
    cudaStreamWaitEvent(0, evWexp, 0);
    gemm_mma<true, true><<<dim3(HDIM / BN, MAX_TILES), 256, SMEM_TOTAL>>>(
        y_h, y_l, wexp, eb, nullptr, z_h, z_l, HDIM, HDIM);

    // join post weights, then post GEMM
    cudaStreamWaitEvent(0, evWpost, 0);
    gemm_mma<false, false><<<dim3(OUTDIM / BN, BDIM / BM), 256, SMEM_TOTAL>>>(
        z_h, z_l, wpost, pb, out, nullptr, nullptr, HDIM, OUTDIM);
}

// round 6
// speedup vs baseline: 6.4707x; 1.6187x over previous
#include <cuda_runtime.h>
#include <cuda_fp16.h>
#include <cstdint>
#include <math.h>

#define BDIM 4096
#define INDIM 1024
#define HDIM 2048
#define OUTDIM 1024
#define EDIM 16
#define MAX_TILES 48

// ---------------- scratch (__device__ globals; no allocation allowed) ----------------
__device__ __half g_obs[BDIM * INDIM];
__device__ __half g_y[BDIM * HDIM];
__device__ __half g_z[BDIM * HDIM];
__device__ __half g_wpre[HDIM * INDIM];
__device__ __half g_wexp[EDIM * HDIM * HDIM];
__device__ __half g_wpost[OUTDIM * HDIM];
__device__ int g_perm[BDIM];
__device__ int g_tile_expert[MAX_TILES];
__device__ int g_tile_row0[MAX_TILES];
__device__ int g_tile_nrows[MAX_TILES];

// ---------------- fused routing: histogram + tiles + scatter, one block ----------------
__global__ __launch_bounds__(512) void k_route(const int* __restrict__ idx) {
    __shared__ int cnt[EDIM];
    __shared__ int cur[EDIM];
    int tid = threadIdx.x;
    if (tid < EDIM) cnt[tid] = 0;
    __syncthreads();
#pragma unroll
    for (int i = 0; i < BDIM / 512; i++)
        atomicAdd(&cnt[idx[tid + i * 512]], 1);
    __syncthreads();
    if (tid == 0) {
        int off = 0, t = 0;
        for (int e = 0; e < EDIM; e++) {
            int n = cnt[e];
            cur[e] = off;
            int nt = (n + 127) >> 7;
            for (int i = 0; i < nt; i++) {
                g_tile_expert[t] = e;
                g_tile_row0[t] = off + (i << 7);
                int rem = n - (i << 7);
                g_tile_nrows[t] = rem < 128 ? rem : 128;
                t++;
            }
            off += n;
        }
        for (; t < MAX_TILES; t++) g_tile_expert[t] = -1;
    }
    __syncthreads();
#pragma unroll
    for (int i = 0; i < BDIM / 512; i++) {
        int b = tid + i * 512;
        int p = atomicAdd(&cur[idx[b]], 1);
        g_perm[p] = b;
    }
}

// ---------------- fp32 -> fp16 cast ----------------
__global__ __launch_bounds__(256) void k_tohalf(const float* __restrict__ in,
                                                __half* __restrict__ h, int n4) {
    int i = blockIdx.x * blockDim.x + threadIdx.x;
    if (i >= n4) return;
    float4 v = ((const float4*)in)[i];
    ((__half2*)h)[i * 2 + 0] = __floats2half2_rn(v.x, v.y);
    ((__half2*)h)[i * 2 + 1] = __floats2half2_rn(v.z, v.w);
}

// ---------------- PTX helpers ----------------
__device__ __forceinline__ uint32_t smem_to_u32(const void* p) {
    uint32_t a;
    asm("{ .reg .u64 t; cvta.to.shared.u64 t, %1; cvt.u32.u64 %0, t; }" : "=r"(a) : "l"(p));
    return a;
}
#define CP16(dst, src) \
    asm volatile("cp.async.cg.shared.global [%0], [%1], 16;" :: "r"(dst), "l"(src))
#define CP_COMMIT() asm volatile("cp.async.commit_group;" ::: "memory")
#define CP_WAIT2() asm volatile("cp.async.wait_group 2;" ::: "memory")
#define LDSM4(r, addr) \
    asm volatile("ldmatrix.sync.aligned.m8n8.x4.shared.b16 {%0,%1,%2,%3}, [%4];" \
        : "=r"((r)[0]), "=r"((r)[1]), "=r"((r)[2]), "=r"((r)[3]) : "r"(addr))
#define MMA(c, a, b0, b1) \
    asm volatile("mma.sync.aligned.m16n8k16.row.col.f32.f16.f16.f32 " \
        "{%0,%1,%2,%3}, {%4,%5,%6,%7}, {%8,%9}, {%0,%1,%2,%3};" \
        : "+f"((c)[0]), "+f"((c)[1]), "+f"((c)[2]), "+f"((c)[3]) \
        : "r"((a)[0]), "r"((a)[1]), "r"((a)[2]), "r"((a)[3]), "r"(b0), "r"(b1))
#define SWZ(off) ((off) ^ (((off) >> 3) & 0x70))

// ---------------- GEMM config ----------------
#define BM 128
#define BN 256
#define BK 64
#define STAGES 4
#define A_TILE_B 16384          // 128x64 fp16
#define B_TILE_B 32768          // 256x64 fp16
#define STAGE_B (A_TILE_B + B_TILE_B)       // 48KB
#define SM_STAGE0 1024
#define SMEM_TOTAL (SM_STAGE0 + STAGES * STAGE_B)   // 197632

// C[M,N] = tanh(A @ W^T + bias); single-pass fp16, fp32 accumulate.
// grid: x = N-block (L2 A-reuse within a wave), y = M-tile
template <bool GATHER, bool OUT_HALF>
__global__ __launch_bounds__(256, 1) void gemm_mma(
    const __half* __restrict__ Ah, const __half* __restrict__ Wh,
    const float* __restrict__ bias,
    float* __restrict__ Cf, __half* __restrict__ Ch,
    int K, int ldc) {
    extern __shared__ char smem[];
    int tid = threadIdx.x, lane = tid & 31, wid = tid >> 5;
    int* permS = (int*)smem;

    int nrows = BM;
    if (GATHER) {
        int e = g_tile_expert[blockIdx.y];
        if (e < 0) return;
        nrows = g_tile_nrows[blockIdx.y];
        int row0 = g_tile_row0[blockIdx.y];
        Wh += (size_t)e * HDIM * HDIM;
        bias += (size_t)e * HDIM;
        if (tid < BM) {
            int rr = tid < nrows ? tid : nrows - 1;
            permS[tid] = g_perm[row0 + rr];
        }
    } else {
        Ah += (size_t)blockIdx.y * BM * K;
    }
    int n0 = blockIdx.x * BN;
    __syncthreads();

    uint32_t sb = smem_to_u32(smem);

    uint32_t swa[4], swb[8];
    const __half *ah_src[4], *bh_src[8];
#pragma unroll
    for (int i = 0; i < 4; i++) {
        int idx = tid + i * 256;
        int r = idx >> 3;
        int cb = (idx & 7) * 16;
        swa[i] = SWZ(r * 128 + cb);
        int ar = GATHER ? permS[r] : r;
        ah_src[i] = Ah + (size_t)ar * K + (cb >> 1);
    }
#pragma unroll
    for (int i = 0; i < 8; i++) {
        int idx = tid + i * 256;
        int r = idx >> 3;
        int cb = (idx & 7) * 16;
        swb[i] = SWZ(r * 128 + cb);
        bh_src[i] = Wh + (size_t)(n0 + r) * K + (cb >> 1);
    }

    auto issue = [&](int stage, int kc) {
        uint32_t base = sb + SM_STAGE0 + stage * STAGE_B;
#pragma unroll
        for (int i = 0; i < 4; i++)
            CP16(base + swa[i], ah_src[i] + kc);
#pragma unroll
        for (int i = 0; i < 8; i++)
            CP16(base + A_TILE_B + swb[i], bh_src[i] + kc);
    };

    int NC = K / BK;
    issue(0, 0); CP_COMMIT();
    issue(1, BK); CP_COMMIT();
    issue(2, 2 * BK); CP_COMMIT();

    float acc[4][8][4];
#pragma unroll
    for (int m = 0; m < 4; m++)
#pragma unroll
        for (int n = 0; n < 8; n++)
#pragma unroll
            for (int q = 0; q < 4; q++) acc[m][n][q] = 0.f;

    int wm = wid >> 2;
    int wn = wid & 3;
    int arow = (lane & 7) + ((lane >> 3) & 1) * 8;
    int brow = (lane & 7) + ((lane >> 4) & 1) * 8;

    for (int c = 0; c < NC; c++) {
        CP_WAIT2();
        __syncthreads();
        if (c + 3 < NC) issue((c + 3) & 3, (c + 3) * BK);
        CP_COMMIT();
        uint32_t base = sb + SM_STAGE0 + (c & 3) * STAGE_B;
#pragma unroll
        for (int kk = 0; kk < 4; kk++) {
            int k0 = kk * 16;
            int acol = k0 + (lane >> 4) * 8;
            int bcol = k0 + ((lane >> 3) & 1) * 8;
            uint32_t ah[4][4];
#pragma unroll
            for (int m = 0; m < 4; m++) {
                uint32_t off = SWZ((wm * 64 + m * 16 + arow) * 128 + acol * 2);
                LDSM4(ah[m], base + off);
            }
            uint32_t bh[4][4];
#pragma unroll
            for (int p = 0; p < 4; p++) {
                uint32_t off = SWZ((wn * 64 + p * 16 + brow) * 128 + bcol * 2);
                LDSM4(bh[p], base + A_TILE_B + off);
            }
#pragma unroll
            for (int m = 0; m < 4; m++)
#pragma unroll
                for (int n = 0; n < 8; n++) {
                    uint32_t b0 = bh[n >> 1][(n & 1) * 2];
                    uint32_t b1 = bh[n >> 1][(n & 1) * 2 + 1];
                    MMA(acc[m][n], ah[m], b0, b1);
                }
        }
    }

    int g = lane >> 2, t4 = lane & 3;
#pragma unroll
    for (int m = 0; m < 4; m++) {
#pragma unroll
        for (int half_ = 0; half_ < 2; half_++) {
            int rl = wm * 64 + m * 16 + g + half_ * 8;
            if (GATHER && rl >= nrows) continue;
            int grow = GATHER ? permS[rl] : blockIdx.y * BM + rl;
#pragma unroll
            for (int n = 0; n < 8; n++) {
                int col = n0 + wn * 64 + n * 8 + t4 * 2;
                float v0 = tanhf(acc[m][n][half_ * 2 + 0] + bias[col]);
                float v1 = tanhf(acc[m][n][half_ * 2 + 1] + bias[col + 1]);
                if (OUT_HALF) {
                    *(__half2*)(Ch + (size_t)grow * ldc + col) = __floats2half2_rn(v0, v1);
                } else {
                    *(float2*)(Cf + (size_t)grow * ldc + col) = make_float2(v0, v1);
                }
            }
        }
    }
}

// ---------------- launch ----------------
extern "C" void kernel_launch(void* const* d_in, const int* in_sizes, int n_in,
                              void* d_out, int out_size) {
    const float* obs   = (const float*)d_in[0];
    const int*   swidx = (const int*)d_in[1];
    const float* pre_w = (const float*)d_in[2];
    const float* pre_b = (const float*)d_in[3];
    const float* ew    = (const float*)d_in[4];
    const float* eb    = (const float*)d_in[5];
    const float* pw    = (const float*)d_in[6];
    const float* pb    = (const float*)d_in[7];
    float* out = (float*)d_out;

    __half *obs_h, *y_h, *z_h, *wpre, *wexp, *wpost;
    cudaGetSymbolAddress((void**)&obs_h, g_obs);
    cudaGetSymbolAddress((void**)&y_h, g_y);
    cudaGetSymbolAddress((void**)&z_h, g_z);
    cudaGetSymbolAddress((void**)&wpre, g_wpre);
    cudaGetSymbolAddress((void**)&wexp, g_wexp);
    cudaGetSymbolAddress((void**)&wpost, g_wpost);

    static cudaStream_t sR = nullptr, sC = nullptr;
    static cudaEvent_t evFork, evRoute, evWexp, evWpost;
    if (!sR) {
        cudaStreamCreateWithFlags(&sR, cudaStreamNonBlocking);
        cudaStreamCreateWithFlags(&sC, cudaStreamNonBlocking);
        cudaEventCreateWithFlags(&evFork, cudaEventDisableTiming);
        cudaEventCreateWithFlags(&evRoute, cudaEventDisableTiming);
        cudaEventCreateWithFlags(&evWexp, cudaEventDisableTiming);
        cudaEventCreateWithFlags(&evWpost, cudaEventDisableTiming);
        cudaFuncSetAttribute(gemm_mma<false, true>,
                             cudaFuncAttributeMaxDynamicSharedMemorySize, SMEM_TOTAL);
        cudaFuncSetAttribute(gemm_mma<true, true>,
                             cudaFuncAttributeMaxDynamicSharedMemorySize, SMEM_TOTAL);
        cudaFuncSetAttribute(gemm_mma<false, false>,
                             cudaFuncAttributeMaxDynamicSharedMemorySize, SMEM_TOTAL);
    }

    // fork side streams
    cudaEventRecord(evFork, 0);
    cudaStreamWaitEvent(sR, evFork, 0);
    cudaStreamWaitEvent(sC, evFork, 0);

    // routing (single fused kernel) on sR
    k_route<<<1, 512, 0, sR>>>(swidx);
    cudaEventRecord(evRoute, sR);

    // big weight converts on sC
    {
        int n4 = EDIM * HDIM * HDIM / 4;
        k_tohalf<<<(n4 + 255) / 256, 256, 0, sC>>>(ew, wexp, n4);
        cudaEventRecord(evWexp, sC);
        n4 = OUTDIM * HDIM / 4;
        k_tohalf<<<(n4 + 255) / 256, 256, 0, sC>>>(pw, wpost, n4);
        cudaEventRecord(evWpost, sC);
    }

    // critical path: obs + wpre converts -> pre GEMM
    {
        int n4 = BDIM * INDIM / 4;
        k_tohalf<<<(n4 + 255) / 256, 256>>>(obs, obs_h, n4);
        n4 = HDIM * INDIM / 4;
        k_tohalf<<<(n4 + 255) / 256, 256>>>(pre_w, wpre, n4);
    }
    // pre: y = tanh(obs @ pre_w^T + pre_b): M=4096, N=2048, K=1024
    gemm_mma<false, true><<<dim3(HDIM / BN, BDIM / BM), 256, SMEM_TOTAL>>>(
        obs_h, wpre, pre_b, nullptr, y_h, INDIM, HDIM);

    // join routing + expert weights, then expert GEMM
    cudaStreamWaitEvent(0, evRoute, 0);
    cudaStreamWaitEvent(0, evWexp, 0);
    gemm_mma<true, true><<<dim3(HDIM / BN, MAX_TILES), 256, SMEM_TOTAL>>>(
        y_h, wexp, eb, nullptr, z_h, HDIM, HDIM);

    // join post weights, then post GEMM
    cudaStreamWaitEvent(0, evWpost, 0);
    gemm_mma<false, false><<<dim3(OUTDIM / BN, BDIM / BM), 256, SMEM_TOTAL>>>(
        z_h, wpost, pb, out, nullptr, HDIM, OUTDIM);
}